// round 3
// baseline (speedup 1.0000x reference)
#include <cuda_runtime.h>
#include <math.h>
#include <stdint.h>

#define IMG 32
#define HDIM 1024
#define WDIM 1024
#define NBLK_X 128
#define LOSS_THR 120.0f
#define MM_BLOCKS 2048

// ---- global scratch (module-scope: no runtime allocations) ----
__device__ float g_part_max[MM_BLOCKS];
__device__ float g_part_min[MM_BLOCKS];
__device__ unsigned int g_count = 0;   // self-resetting -> deterministic across graph replays
__device__ float g_mx;
__device__ float g_mn;

// Phase A: global min/max of width-deltas xd = x - shift_right(x).
// Per-CTA partials + last-CTA final reduce (threadfence reduction pattern).
__global__ __launch_bounds__(256) void minmax_kernel(const float* __restrict__ x) {
    const int n4 = (IMG * HDIM * WDIM) / 4;
    const int tid = threadIdx.x;
    const int lane = tid & 31;
    const int warp = tid >> 5;
    const int stride = gridDim.x * blockDim.x;

    float vmax = -3.402823466e38f, vmin = 3.402823466e38f;
    for (int t = blockIdx.x * blockDim.x + tid; t < n4; t += stride) {
        float4 v = reinterpret_cast<const float4*>(x)[t];
        int e = t << 2;
        float pw = __shfl_up_sync(0xFFFFFFFFu, v.w, 1);
        float left;
        if (lane == 0)
            left = ((e & (WDIM - 1)) == 0) ? 0.0f : __ldg(x + e - 1);
        else
            left = pw;
        float d0 = v.x - left;
        float d1 = v.y - v.x;
        float d2 = v.z - v.y;
        float d3 = v.w - v.z;
        vmax = fmaxf(fmaxf(fmaxf(d0, d1), fmaxf(d2, d3)), vmax);
        vmin = fminf(fminf(fminf(d0, d1), fminf(d2, d3)), vmin);
    }
    for (int o = 16; o; o >>= 1) {
        vmax = fmaxf(vmax, __shfl_xor_sync(0xFFFFFFFFu, vmax, o));
        vmin = fminf(vmin, __shfl_xor_sync(0xFFFFFFFFu, vmin, o));
    }
    __shared__ float swmax[8], swmin[8];
    if (lane == 0) { swmax[warp] = vmax; swmin[warp] = vmin; }
    __syncthreads();
    if (tid == 0) {
        float bmax = swmax[0], bmin = swmin[0];
        #pragma unroll
        for (int k = 1; k < 8; k++) {
            bmax = fmaxf(bmax, swmax[k]);
            bmin = fminf(bmin, swmin[k]);
        }
        g_part_max[blockIdx.x] = bmax;
        g_part_min[blockIdx.x] = bmin;
    }

    // last CTA reduces all partials
    __shared__ bool isLast;
    if (tid == 0) {
        __threadfence();
        unsigned int c = atomicAdd(&g_count, 1u);
        isLast = (c == gridDim.x - 1);
    }
    __syncthreads();
    if (isLast) {
        float mx = -3.402823466e38f, mn = 3.402823466e38f;
        for (int j = tid; j < MM_BLOCKS; j += blockDim.x) {
            mx = fmaxf(mx, g_part_max[j]);
            mn = fminf(mn, g_part_min[j]);
        }
        for (int o = 16; o; o >>= 1) {
            mx = fmaxf(mx, __shfl_xor_sync(0xFFFFFFFFu, mx, o));
            mn = fminf(mn, __shfl_xor_sync(0xFFFFFFFFu, mn, o));
        }
        if (lane == 0) { swmax[warp] = mx; swmin[warp] = mn; }
        __syncthreads();
        if (tid == 0) {
            float bmax = swmax[0], bmin = swmin[0];
            #pragma unroll
            for (int k = 1; k < 8; k++) {
                bmax = fmaxf(bmax, swmax[k]);
                bmin = fminf(bmin, swmin[k]);
            }
            g_mx = bmax;
            g_mn = bmin;
            g_count = 0;  // reset for next replay (deterministic)
        }
    }
}

// Phase B: one CTA per 8x8 spatial block (wb, hb); 32 images x 64 pixels.
__global__ __launch_bounds__(256) void block_kernel(const float* __restrict__ x,
                                                    float* __restrict__ out) {
    __shared__ float sd1[IMG][68];   // dequant deltas; 68: 16B-aligned rows, stride%32=4
    __shared__ float sxl[IMG][68];   // x_left
    __shared__ float sbase[3][64];   // inv(AT_A) @ a_base
    __shared__ float sp[3][IMG];     // projection coeffs
    __shared__ float sS[5];
    __shared__ int   sdegen;

    const int tid = threadIdx.x;
    const int warp = tid >> 5;
    const int lane = tid & 31;
    const int wb = blockIdx.x & (NBLK_X - 1);
    const int hb = blockIdx.x >> 7;

    const float mx = g_mx, mn = g_mn;
    const bool neq = (mx != mn);
    const float scale = neq ? __fdiv_rn(65535.0f, __fsub_rn(mx, mn)) : 1.0f;
    const float s_inv = __fdiv_rn(1.0f, scale);
    const float m = neq ? mn : 0.0f;
    const float lsb = exp2f(rintf(log2f(__fdiv_rn(mx, 32768.0f))) + 1.0f);
    const float rlsb = __fdiv_rn(1.0f, lsb);

    // ---- vectorized load + delta + quant-dequant ----
    {
        int i = tid >> 3, row = tid & 7;
        int g = (i << 20) + (((hb << 3) + row) << 10) + (wb << 3);
        float4 v0 = *reinterpret_cast<const float4*>(x + g);
        float4 v1 = *reinterpret_cast<const float4*>(x + g + 4);
        float left = (wb == 0) ? 0.0f : __ldg(x + g - 1);
        float xv[8] = {v0.x, v0.y, v0.z, v0.w, v1.x, v1.y, v1.z, v1.w};
        float xl[8];
        xl[0] = left;
        #pragma unroll
        for (int c = 1; c < 8; c++) xl[c] = xv[c - 1];
        float q1[8];
        #pragma unroll
        for (int c = 0; c < 8; c++) {
            float xd = __fsub_rn(xv[c], xl[c]);
            if (neq) {
                float q = rintf(__fmul_rn(__fsub_rn(xd, mn), scale));
                q1[c] = __fadd_rn(__fmul_rn(q, s_inv), m);
            } else {
                q1[c] = xd;
            }
        }
        float* dp = &sd1[i][row << 3];
        float* lp = &sxl[i][row << 3];
        *reinterpret_cast<float4*>(dp)     = make_float4(q1[0], q1[1], q1[2], q1[3]);
        *reinterpret_cast<float4*>(dp + 4) = make_float4(q1[4], q1[5], q1[6], q1[7]);
        *reinterpret_cast<float4*>(lp)     = make_float4(xl[0], xl[1], xl[2], xl[3]);
        *reinterpret_cast<float4*>(lp + 4) = make_float4(xl[4], xl[5], xl[6], xl[7]);
    }
    __syncthreads();

    // ---- Gram matrix + degeneracy (warp 0) ----
    if (warp == 0) {
        float a1a = sd1[0][lane], a1b = sd1[0][lane + 32];
        float a2a = sd1[1][lane], a2b = sd1[1][lane + 32];
        float S11 = a1a * a1a + a1b * a1b;
        float S12 = a1a * a2a + a1b * a2b;
        float S1  = a1a + a1b;
        float S22 = a2a * a2a + a2b * a2b;
        float S2  = a2a + a2b;
        float mx1 = fmaxf(a1a, a1b), mn1 = fminf(a1a, a1b);
        float mx2 = fmaxf(a2a, a2b), mn2 = fminf(a2a, a2b);
        for (int o = 16; o; o >>= 1) {
            S11 += __shfl_xor_sync(0xFFFFFFFFu, S11, o);
            S12 += __shfl_xor_sync(0xFFFFFFFFu, S12, o);
            S1  += __shfl_xor_sync(0xFFFFFFFFu, S1, o);
            S22 += __shfl_xor_sync(0xFFFFFFFFu, S22, o);
            S2  += __shfl_xor_sync(0xFFFFFFFFu, S2, o);
            mx1 = fmaxf(mx1, __shfl_xor_sync(0xFFFFFFFFu, mx1, o));
            mn1 = fminf(mn1, __shfl_xor_sync(0xFFFFFFFFu, mn1, o));
            mx2 = fmaxf(mx2, __shfl_xor_sync(0xFFFFFFFFu, mx2, o));
            mn2 = fminf(mn2, __shfl_xor_sync(0xFFFFFFFFu, mn2, o));
        }
        if (lane == 0) {
            sS[0] = S11; sS[1] = S12; sS[2] = S1; sS[3] = S22; sS[4] = S2;
            sdegen = (((mx1 - mn1) < 1e-6f) && ((mx2 - mn2) < 1e-6f)) ? 1 : 0;
        }
    }
    __syncthreads();

    // ---- 3x3 symmetric inverse (redundant per-thread) ----
    const float A00 = sS[0], A01 = sS[1], A02 = sS[2];
    const float A11 = sS[3], A12 = sS[4], A22 = 64.0f;
    float det = A00 * (A11 * A22 - A12 * A12)
              - A01 * (A01 * A22 - A12 * A02)
              + A02 * (A01 * A12 - A11 * A02);
    float i00, i01, i02, i11, i12, i22;
    if (det == 0.0f) {
        i00 = 1.0f; i01 = 0.0f; i02 = 0.0f;
        i11 = 1.0f; i12 = 0.0f; i22 = 1.0f;
    } else {
        i00 = (A11 * A22 - A12 * A12) / det;
        i01 = (A02 * A12 - A01 * A22) / det;
        i02 = (A01 * A12 - A02 * A11) / det;
        i11 = (A00 * A22 - A02 * A02) / det;
        i12 = (A01 * A02 - A00 * A12) / det;
        i22 = (A00 * A11 - A01 * A01) / det;
    }

    // ---- base = inv @ a_base  (3 x 64) ----
    if (tid < 192) {
        int k = tid >> 6;
        int p = tid & 63;
        float c0 = (k == 0) ? i00 : ((k == 1) ? i01 : i02);
        float c1 = (k == 0) ? i01 : ((k == 1) ? i11 : i12);
        float c2 = (k == 0) ? i02 : ((k == 1) ? i12 : i22);
        sbase[k][p] = c0 * sd1[0][p] + c1 * sd1[1][p] + c2;
    }
    __syncthreads();

    // ---- p = base @ d : 96 dots, 12 per warp, row-wise smem access ----
    #pragma unroll
    for (int j = 0; j < 12; j++) {
        int o = warp * 12 + j;
        int k = o >> 5;
        int i = o & 31;
        float t = sbase[k][lane] * sd1[i][lane]
                + sbase[k][lane + 32] * sd1[i][lane + 32];
        for (int of = 16; of; of >>= 1)
            t += __shfl_xor_sync(0xFFFFFFFFu, t, of);
        if (lane == 0) sp[k][i] = t;
    }
    __syncthreads();

    // ---- preload a1/a2 (about to be overwritten in place) ----
    const float a1a = sd1[0][lane], a1b = sd1[0][lane + 32];
    const float a2a = sd1[1][lane], a2b = sd1[1][lane + 32];
    const bool degen = (sdegen != 0);
    __syncthreads();

    // ---- reconstruct, quantize, loss gate; final value written in place ----
    #pragma unroll
    for (int ii = 0; ii < 4; ii++) {
        int i = (warp << 2) + ii;
        float p0 = sp[0][i], p1 = sp[1][i], p2 = sp[2][i];
        float d1a = sd1[i][lane], d1b = sd1[i][lane + 32];
        float ra = a1a * p0 + a2a * p1 + p2;
        float rb = a1b * p0 + a2b * p1 + p2;
        float r1a = __fmul_rn(rintf(__fmul_rn(ra, rlsb)), lsb);
        float r1b = __fmul_rn(rintf(__fmul_rn(rb, rlsb)), lsb);
        float da = d1a - r1a;
        float db = d1b - r1b;
        float loss = da * da + db * db;
        for (int o = 16; o; o >>= 1)
            loss += __shfl_xor_sync(0xFFFFFFFFu, loss, o);
        bool sel = (!degen) && (loss <= LOSS_THR);
        float rra = sel ? r1a : d1a;
        float rrb = sel ? r1b : d1b;
        sd1[i][lane]      = __fadd_rn(rra, sxl[i][lane]);
        sd1[i][lane + 32] = __fadd_rn(rrb, sxl[i][lane + 32]);
    }
    __syncthreads();

    // ---- vectorized store ----
    {
        int i = tid >> 3, row = tid & 7;
        int g = (i << 20) + (((hb << 3) + row) << 10) + (wb << 3);
        const float* dp = &sd1[i][row << 3];
        float4 o0 = *reinterpret_cast<const float4*>(dp);
        float4 o1 = *reinterpret_cast<const float4*>(dp + 4);
        *reinterpret_cast<float4*>(out + g)     = o0;
        *reinterpret_cast<float4*>(out + g + 4) = o1;
    }
}

extern "C" void kernel_launch(void* const* d_in, const int* in_sizes, int n_in,
                              void* d_out, int out_size) {
    const float* x = (const float*)d_in[0];
    float* out = (float*)d_out;
    (void)in_sizes; (void)n_in; (void)out_size;

    minmax_kernel<<<MM_BLOCKS, 256>>>(x);
    block_kernel<<<NBLK_X * NBLK_X, 256>>>(x, out);
}

// round 4
// speedup vs baseline: 1.2991x; 1.2991x over previous
#include <cuda_runtime.h>
#include <math.h>
#include <stdint.h>

#define IMG 32
#define HDIM 1024
#define WDIM 1024
#define NBLK_X 128
#define LOSS_THR 120.0f
#define MM_BLOCKS 2048

// ---- global scratch (module-scope: no runtime allocations) ----
__device__ float g_part_max[MM_BLOCKS];
__device__ float g_part_min[MM_BLOCKS];
__device__ unsigned int g_count = 0;   // self-resetting -> deterministic across graph replays
__device__ float g_mx;
__device__ float g_mn;

// Phase A: global min/max of width-deltas xd = x - shift_right(x).
__global__ __launch_bounds__(256) void minmax_kernel(const float* __restrict__ x) {
    const int n4 = (IMG * HDIM * WDIM) / 4;
    const int tid = threadIdx.x;
    const int lane = tid & 31;
    const int warp = tid >> 5;
    const int stride = gridDim.x * blockDim.x;

    float vmax = -3.402823466e38f, vmin = 3.402823466e38f;
    #pragma unroll 4
    for (int t = blockIdx.x * blockDim.x + tid; t < n4; t += stride) {
        float4 v = reinterpret_cast<const float4*>(x)[t];
        int e = t << 2;
        float pw = __shfl_up_sync(0xFFFFFFFFu, v.w, 1);
        float left;
        if (lane == 0)
            left = ((e & (WDIM - 1)) == 0) ? 0.0f : __ldg(x + e - 1);
        else
            left = pw;
        float d0 = v.x - left;
        float d1 = v.y - v.x;
        float d2 = v.z - v.y;
        float d3 = v.w - v.z;
        vmax = fmaxf(fmaxf(fmaxf(d0, d1), fmaxf(d2, d3)), vmax);
        vmin = fminf(fminf(fminf(d0, d1), fminf(d2, d3)), vmin);
    }
    for (int o = 16; o; o >>= 1) {
        vmax = fmaxf(vmax, __shfl_xor_sync(0xFFFFFFFFu, vmax, o));
        vmin = fminf(vmin, __shfl_xor_sync(0xFFFFFFFFu, vmin, o));
    }
    __shared__ float swmax[8], swmin[8];
    if (lane == 0) { swmax[warp] = vmax; swmin[warp] = vmin; }
    __syncthreads();
    if (tid == 0) {
        float bmax = swmax[0], bmin = swmin[0];
        #pragma unroll
        for (int k = 1; k < 8; k++) {
            bmax = fmaxf(bmax, swmax[k]);
            bmin = fminf(bmin, swmin[k]);
        }
        g_part_max[blockIdx.x] = bmax;
        g_part_min[blockIdx.x] = bmin;
    }

    __shared__ bool isLast;
    if (tid == 0) {
        __threadfence();
        unsigned int c = atomicAdd(&g_count, 1u);
        isLast = (c == gridDim.x - 1);
    }
    __syncthreads();
    if (isLast) {
        float mx = -3.402823466e38f, mn = 3.402823466e38f;
        for (int j = tid; j < MM_BLOCKS; j += blockDim.x) {
            mx = fmaxf(mx, g_part_max[j]);
            mn = fminf(mn, g_part_min[j]);
        }
        for (int o = 16; o; o >>= 1) {
            mx = fmaxf(mx, __shfl_xor_sync(0xFFFFFFFFu, mx, o));
            mn = fminf(mn, __shfl_xor_sync(0xFFFFFFFFu, mn, o));
        }
        if (lane == 0) { swmax[warp] = mx; swmin[warp] = mn; }
        __syncthreads();
        if (tid == 0) {
            float bmax = swmax[0], bmin = swmin[0];
            #pragma unroll
            for (int k = 1; k < 8; k++) {
                bmax = fmaxf(bmax, swmax[k]);
                bmin = fminf(bmin, swmin[k]);
            }
            g_mx = bmax;
            g_mn = bmin;
            g_count = 0;  // reset for next replay
        }
    }
}

// Phase B: one CTA per 8x8 spatial block; thread = (image, row) owns 8 pixels
// in registers end-to-end. smem holds only a1,a2,base,p + scalars.
__global__ __launch_bounds__(256) void block_kernel(const float* __restrict__ x,
                                                    float* __restrict__ out) {
    __shared__ float sa1[64];        // d1 of image 0
    __shared__ float sa2[64];        // d1 of image 1
    __shared__ float sbase[3][64];   // inv(AT_A) @ a_base
    __shared__ float sp[3][IMG];     // projection coeffs
    __shared__ float sS[5];
    __shared__ int   sdegen;

    const int tid = threadIdx.x;
    const int warp = tid >> 5;
    const int lane = tid & 31;
    const int img = tid >> 3;        // image 0..31
    const int row = tid & 7;         // row within 8x8 block
    const int wb = blockIdx.x & (NBLK_X - 1);
    const int hb = blockIdx.x >> 7;

    const float mx = g_mx, mn = g_mn;
    const bool neq = (mx != mn);
    const float scale = neq ? __fdiv_rn(65535.0f, __fsub_rn(mx, mn)) : 1.0f;
    const float s_inv = __fdiv_rn(1.0f, scale);
    const float m = neq ? mn : 0.0f;
    const float lsb = exp2f(rintf(log2f(__fdiv_rn(mx, 32768.0f))) + 1.0f);
    const float rlsb = __fdiv_rn(1.0f, lsb);

    // ---- load one row (8 px) + delta + quant-dequant; d1/xl stay in registers ----
    float d1r[8], xlr[8];
    const int g = (img << 20) + (((hb << 3) + row) << 10) + (wb << 3);
    {
        float4 v0 = *reinterpret_cast<const float4*>(x + g);
        float4 v1 = *reinterpret_cast<const float4*>(x + g + 4);
        float left = (wb == 0) ? 0.0f : __ldg(x + g - 1);
        float xv[8] = {v0.x, v0.y, v0.z, v0.w, v1.x, v1.y, v1.z, v1.w};
        xlr[0] = left;
        #pragma unroll
        for (int c = 1; c < 8; c++) xlr[c] = xv[c - 1];
        #pragma unroll
        for (int c = 0; c < 8; c++) {
            float xd = __fsub_rn(xv[c], xlr[c]);
            if (neq) {
                float q = rintf(__fmul_rn(__fsub_rn(xd, mn), scale));
                d1r[c] = __fadd_rn(__fmul_rn(q, s_inv), m);
            } else {
                d1r[c] = xd;
            }
        }
        if (img < 2) {
            float* dst = (img == 0) ? &sa1[row << 3] : &sa2[row << 3];
            *reinterpret_cast<float4*>(dst)     = make_float4(d1r[0], d1r[1], d1r[2], d1r[3]);
            *reinterpret_cast<float4*>(dst + 4) = make_float4(d1r[4], d1r[5], d1r[6], d1r[7]);
        }
    }
    __syncthreads();

    // ---- Gram matrix + degeneracy (warp 0 only) ----
    if (warp == 0) {
        float a1a = sa1[lane], a1b = sa1[lane + 32];
        float a2a = sa2[lane], a2b = sa2[lane + 32];
        float S11 = a1a * a1a + a1b * a1b;
        float S12 = a1a * a2a + a1b * a2b;
        float S1  = a1a + a1b;
        float S22 = a2a * a2a + a2b * a2b;
        float S2  = a2a + a2b;
        float mx1 = fmaxf(a1a, a1b), mn1 = fminf(a1a, a1b);
        float mx2 = fmaxf(a2a, a2b), mn2 = fminf(a2a, a2b);
        for (int o = 16; o; o >>= 1) {
            S11 += __shfl_xor_sync(0xFFFFFFFFu, S11, o);
            S12 += __shfl_xor_sync(0xFFFFFFFFu, S12, o);
            S1  += __shfl_xor_sync(0xFFFFFFFFu, S1, o);
            S22 += __shfl_xor_sync(0xFFFFFFFFu, S22, o);
            S2  += __shfl_xor_sync(0xFFFFFFFFu, S2, o);
            mx1 = fmaxf(mx1, __shfl_xor_sync(0xFFFFFFFFu, mx1, o));
            mn1 = fminf(mn1, __shfl_xor_sync(0xFFFFFFFFu, mn1, o));
            mx2 = fmaxf(mx2, __shfl_xor_sync(0xFFFFFFFFu, mx2, o));
            mn2 = fminf(mn2, __shfl_xor_sync(0xFFFFFFFFu, mn2, o));
        }
        if (lane == 0) {
            sS[0] = S11; sS[1] = S12; sS[2] = S1; sS[3] = S22; sS[4] = S2;
            sdegen = (((mx1 - mn1) < 1e-6f) && ((mx2 - mn2) < 1e-6f)) ? 1 : 0;
        }
    }
    __syncthreads();

    // ---- 3x3 symmetric inverse (redundant per-thread, registers) ----
    const float A00 = sS[0], A01 = sS[1], A02 = sS[2];
    const float A11 = sS[3], A12 = sS[4], A22 = 64.0f;
    float det = A00 * (A11 * A22 - A12 * A12)
              - A01 * (A01 * A22 - A12 * A02)
              + A02 * (A01 * A12 - A11 * A02);
    float i00, i01, i02, i11, i12, i22;
    if (det == 0.0f) {
        i00 = 1.0f; i01 = 0.0f; i02 = 0.0f;
        i11 = 1.0f; i12 = 0.0f; i22 = 1.0f;
    } else {
        i00 = (A11 * A22 - A12 * A12) / det;
        i01 = (A02 * A12 - A01 * A22) / det;
        i02 = (A01 * A12 - A02 * A11) / det;
        i11 = (A00 * A22 - A02 * A02) / det;
        i12 = (A01 * A02 - A00 * A12) / det;
        i22 = (A00 * A11 - A01 * A01) / det;
    }

    // ---- base = inv @ a_base  (3 x 64) ----
    if (tid < 192) {
        int k = tid >> 6;
        int p = tid & 63;
        float c0 = (k == 0) ? i00 : ((k == 1) ? i01 : i02);
        float c1 = (k == 0) ? i01 : ((k == 1) ? i11 : i12);
        float c2 = (k == 0) ? i02 : ((k == 1) ? i12 : i22);
        sbase[k][p] = c0 * sa1[p] + c1 * sa2[p] + c2;
    }
    __syncthreads();

    // ---- p[k][img] = sum_p base[k][p] * d1[img][p], d1 from registers ----
    {
        float t0 = 0.0f, t1 = 0.0f, t2 = 0.0f;
        const float* b0 = &sbase[0][row << 3];
        const float* b1 = &sbase[1][row << 3];
        const float* b2 = &sbase[2][row << 3];
        float4 b0a = *reinterpret_cast<const float4*>(b0);
        float4 b0b = *reinterpret_cast<const float4*>(b0 + 4);
        float4 b1a = *reinterpret_cast<const float4*>(b1);
        float4 b1b = *reinterpret_cast<const float4*>(b1 + 4);
        float4 b2a = *reinterpret_cast<const float4*>(b2);
        float4 b2b = *reinterpret_cast<const float4*>(b2 + 4);
        float bb0[8] = {b0a.x, b0a.y, b0a.z, b0a.w, b0b.x, b0b.y, b0b.z, b0b.w};
        float bb1[8] = {b1a.x, b1a.y, b1a.z, b1a.w, b1b.x, b1b.y, b1b.z, b1b.w};
        float bb2[8] = {b2a.x, b2a.y, b2a.z, b2a.w, b2b.x, b2b.y, b2b.z, b2b.w};
        #pragma unroll
        for (int c = 0; c < 8; c++) {
            t0 += bb0[c] * d1r[c];
            t1 += bb1[c] * d1r[c];
            t2 += bb2[c] * d1r[c];
        }
        // reduce over the 8 lanes (rows) of this image
        #pragma unroll
        for (int o = 4; o; o >>= 1) {
            t0 += __shfl_xor_sync(0xFFFFFFFFu, t0, o);
            t1 += __shfl_xor_sync(0xFFFFFFFFu, t1, o);
            t2 += __shfl_xor_sync(0xFFFFFFFFu, t2, o);
        }
        if (row == 0) {
            sp[0][img] = t0;
            sp[1][img] = t1;
            sp[2][img] = t2;
        }
    }
    __syncthreads();

    // ---- reconstruct, quantize, loss gate, store (all from registers) ----
    {
        const bool degen = (sdegen != 0);
        const float p0 = sp[0][img], p1 = sp[1][img], p2 = sp[2][img];
        const float* a1p = &sa1[row << 3];
        const float* a2p = &sa2[row << 3];
        float4 a1a = *reinterpret_cast<const float4*>(a1p);
        float4 a1b = *reinterpret_cast<const float4*>(a1p + 4);
        float4 a2a = *reinterpret_cast<const float4*>(a2p);
        float4 a2b = *reinterpret_cast<const float4*>(a2p + 4);
        float av1[8] = {a1a.x, a1a.y, a1a.z, a1a.w, a1b.x, a1b.y, a1b.z, a1b.w};
        float av2[8] = {a2a.x, a2a.y, a2a.z, a2a.w, a2b.x, a2b.y, a2b.z, a2b.w};

        float r1v[8];
        float loss = 0.0f;
        #pragma unroll
        for (int c = 0; c < 8; c++) {
            float r = av1[c] * p0 + av2[c] * p1 + p2;
            r1v[c] = __fmul_rn(rintf(__fmul_rn(r, rlsb)), lsb);
            float d = d1r[c] - r1v[c];
            loss += d * d;
        }
        #pragma unroll
        for (int o = 4; o; o >>= 1)
            loss += __shfl_xor_sync(0xFFFFFFFFu, loss, o);

        bool sel = (!degen) && (loss <= LOSS_THR);
        float ov[8];
        #pragma unroll
        for (int c = 0; c < 8; c++) {
            float rr = sel ? r1v[c] : d1r[c];
            ov[c] = __fadd_rn(rr, xlr[c]);
        }
        *reinterpret_cast<float4*>(out + g)     = make_float4(ov[0], ov[1], ov[2], ov[3]);
        *reinterpret_cast<float4*>(out + g + 4) = make_float4(ov[4], ov[5], ov[6], ov[7]);
    }
}

extern "C" void kernel_launch(void* const* d_in, const int* in_sizes, int n_in,
                              void* d_out, int out_size) {
    const float* x = (const float*)d_in[0];
    float* out = (float*)d_out;
    (void)in_sizes; (void)n_in; (void)out_size;

    minmax_kernel<<<MM_BLOCKS, 256>>>(x);
    block_kernel<<<NBLK_X * NBLK_X, 256>>>(x, out);
}

// round 5
// speedup vs baseline: 1.7432x; 1.3418x over previous
#include <cuda_runtime.h>
#include <math.h>
#include <stdint.h>

#define IMG 32
#define HDIM 1024
#define WDIM 1024
#define LOSS_THR 120.0f
#define MM_BLOCKS 2048
#define NWBG 32          // 1024 / 32 px per CTA
#define NHB 128

// ---- global scratch (module-scope: no runtime allocations) ----
__device__ float g_part_max[MM_BLOCKS];
__device__ float g_part_min[MM_BLOCKS];
__device__ unsigned int g_count = 0;   // self-resetting -> deterministic across graph replays
__device__ float g_mx;
__device__ float g_mn;

// Phase A: global min/max of width-deltas xd = x - shift_right(x).
__global__ __launch_bounds__(256) void minmax_kernel(const float* __restrict__ x) {
    const int n4 = (IMG * HDIM * WDIM) / 4;
    const int tid = threadIdx.x;
    const int lane = tid & 31;
    const int warp = tid >> 5;
    const int stride = gridDim.x * blockDim.x;

    float vmax = -3.402823466e38f, vmin = 3.402823466e38f;
    #pragma unroll 4
    for (int t = blockIdx.x * blockDim.x + tid; t < n4; t += stride) {
        float4 v = reinterpret_cast<const float4*>(x)[t];
        int e = t << 2;
        float pw = __shfl_up_sync(0xFFFFFFFFu, v.w, 1);
        float left;
        if (lane == 0)
            left = ((e & (WDIM - 1)) == 0) ? 0.0f : __ldg(x + e - 1);
        else
            left = pw;
        float d0 = v.x - left;
        float d1 = v.y - v.x;
        float d2 = v.z - v.y;
        float d3 = v.w - v.z;
        vmax = fmaxf(fmaxf(fmaxf(d0, d1), fmaxf(d2, d3)), vmax);
        vmin = fminf(fminf(fminf(d0, d1), fminf(d2, d3)), vmin);
    }
    for (int o = 16; o; o >>= 1) {
        vmax = fmaxf(vmax, __shfl_xor_sync(0xFFFFFFFFu, vmax, o));
        vmin = fminf(vmin, __shfl_xor_sync(0xFFFFFFFFu, vmin, o));
    }
    __shared__ float swmax[8], swmin[8];
    if (lane == 0) { swmax[warp] = vmax; swmin[warp] = vmin; }
    __syncthreads();
    if (tid == 0) {
        float bmax = swmax[0], bmin = swmin[0];
        #pragma unroll
        for (int k = 1; k < 8; k++) {
            bmax = fmaxf(bmax, swmax[k]);
            bmin = fminf(bmin, swmin[k]);
        }
        g_part_max[blockIdx.x] = bmax;
        g_part_min[blockIdx.x] = bmin;
    }

    __shared__ bool isLast;
    if (tid == 0) {
        __threadfence();
        unsigned int c = atomicAdd(&g_count, 1u);
        isLast = (c == gridDim.x - 1);
    }
    __syncthreads();
    if (isLast) {
        float mx = -3.402823466e38f, mn = 3.402823466e38f;
        for (int j = tid; j < MM_BLOCKS; j += blockDim.x) {
            mx = fmaxf(mx, g_part_max[j]);
            mn = fminf(mn, g_part_min[j]);
        }
        for (int o = 16; o; o >>= 1) {
            mx = fmaxf(mx, __shfl_xor_sync(0xFFFFFFFFu, mx, o));
            mn = fminf(mn, __shfl_xor_sync(0xFFFFFFFFu, mn, o));
        }
        if (lane == 0) { swmax[warp] = mx; swmin[warp] = mn; }
        __syncthreads();
        if (tid == 0) {
            float bmax = swmax[0], bmin = swmin[0];
            #pragma unroll
            for (int k = 1; k < 8; k++) {
                bmax = fmaxf(bmax, swmax[k]);
                bmin = fminf(bmin, swmin[k]);
            }
            g_mx = bmax;
            g_mn = bmin;
            g_count = 0;  // reset for next replay
        }
    }
}

// Phase B: one CTA per (hb, group of 4 adjacent 8x8 blocks).
// Coalesced float4 staging global->smem, register pipeline per sub-block, staged store.
__global__ __launch_bounds__(256) void block_kernel(const float* __restrict__ x,
                                                    float* __restrict__ out) {
    __shared__ float ss[256][36];      // (img*8+row) strips of 32 px; stride 36: LDS.128 conflict-free
    __shared__ float sa[2][8][12];     // d1 of images 0,1 (row-major, padded)
    __shared__ float sbase[3][8][12];  // inv(AT_A) @ a_base, padded
    __shared__ float sp[3][IMG];       // projection coeffs
    __shared__ float sS[5];
    __shared__ int   sdegen;

    const int tid = threadIdx.x;
    const int lane = tid & 31;
    const int warp = tid >> 5;
    const int img = tid >> 3;          // image 0..31
    const int row = tid & 7;           // row 0..7
    const int wbg = blockIdx.x & (NWBG - 1);
    const int hb = blockIdx.x >> 5;

    const float mx = g_mx, mn = g_mn;
    const bool neq = (mx != mn);
    const float scale = neq ? __fdiv_rn(65535.0f, __fsub_rn(mx, mn)) : 1.0f;
    const float s_inv = __fdiv_rn(1.0f, scale);
    const float m = neq ? mn : 0.0f;
    const float lsb = exp2f(rintf(log2f(__fdiv_rn(mx, 32768.0f))) + 1.0f);
    const float rlsb = __fdiv_rn(1.0f, lsb);

    // ---- coalesced staging: global -> smem (4 wavefronts per warp-instr) ----
    #pragma unroll
    for (int k = 0; k < 8; k++) {
        int f = (k << 8) + tid;        // float4 index 0..2047
        int seg = f >> 3;              // strip 0..255
        int j = f & 7;                 // float4 within strip
        int si = seg >> 3, sr = seg & 7;
        float4 v = *reinterpret_cast<const float4*>(
            x + (si << 20) + (((hb << 3) + sr) << 10) + (wbg << 5) + (j << 2));
        *reinterpret_cast<float4*>(&ss[seg][j << 2]) = v;
    }
    // boundary left pixel for this thread's strip (col = wbg*32 - 1)
    float carry = 0.0f;
    if (wbg > 0)
        carry = __ldg(x + (img << 20) + (((hb << 3) + row) << 10) + (wbg << 5) - 1);
    __syncthreads();

    const int gout = (img << 20) + (((hb << 3) + row) << 10) + (wbg << 5);

    for (int wb = 0; wb < 4; wb++) {
        // ---- read own 8 px from smem, delta + quant-dequant in registers ----
        float4 v0 = *reinterpret_cast<const float4*>(&ss[tid][wb << 3]);
        float4 v1 = *reinterpret_cast<const float4*>(&ss[tid][(wb << 3) + 4]);
        float xv[8] = {v0.x, v0.y, v0.z, v0.w, v1.x, v1.y, v1.z, v1.w};
        float xl[8], d1r[8];
        xl[0] = carry;
        #pragma unroll
        for (int c = 1; c < 8; c++) xl[c] = xv[c - 1];
        carry = xv[7];
        #pragma unroll
        for (int c = 0; c < 8; c++) {
            float xd = __fsub_rn(xv[c], xl[c]);
            if (neq) {
                float q = rintf(__fmul_rn(__fsub_rn(xd, mn), scale));
                d1r[c] = __fadd_rn(__fmul_rn(q, s_inv), m);
            } else {
                d1r[c] = xd;
            }
        }
        if (img < 2) {
            float* dst = &sa[img][row][0];
            *reinterpret_cast<float4*>(dst)     = make_float4(d1r[0], d1r[1], d1r[2], d1r[3]);
            *reinterpret_cast<float4*>(dst + 4) = make_float4(d1r[4], d1r[5], d1r[6], d1r[7]);
        }
        __syncthreads();

        // ---- Gram matrix + degeneracy (warp 0) ----
        if (warp == 0) {
            int r0 = lane >> 3, c0i = lane & 7;
            float a1a = sa[0][r0][c0i],     a1b = sa[0][r0 + 4][c0i];
            float a2a = sa[1][r0][c0i],     a2b = sa[1][r0 + 4][c0i];
            float S11 = a1a * a1a + a1b * a1b;
            float S12 = a1a * a2a + a1b * a2b;
            float S1  = a1a + a1b;
            float S22 = a2a * a2a + a2b * a2b;
            float S2  = a2a + a2b;
            float mx1 = fmaxf(a1a, a1b), mn1 = fminf(a1a, a1b);
            float mx2 = fmaxf(a2a, a2b), mn2 = fminf(a2a, a2b);
            for (int o = 16; o; o >>= 1) {
                S11 += __shfl_xor_sync(0xFFFFFFFFu, S11, o);
                S12 += __shfl_xor_sync(0xFFFFFFFFu, S12, o);
                S1  += __shfl_xor_sync(0xFFFFFFFFu, S1, o);
                S22 += __shfl_xor_sync(0xFFFFFFFFu, S22, o);
                S2  += __shfl_xor_sync(0xFFFFFFFFu, S2, o);
                mx1 = fmaxf(mx1, __shfl_xor_sync(0xFFFFFFFFu, mx1, o));
                mn1 = fminf(mn1, __shfl_xor_sync(0xFFFFFFFFu, mn1, o));
                mx2 = fmaxf(mx2, __shfl_xor_sync(0xFFFFFFFFu, mx2, o));
                mn2 = fminf(mn2, __shfl_xor_sync(0xFFFFFFFFu, mn2, o));
            }
            if (lane == 0) {
                sS[0] = S11; sS[1] = S12; sS[2] = S1; sS[3] = S22; sS[4] = S2;
                sdegen = (((mx1 - mn1) < 1e-6f) && ((mx2 - mn2) < 1e-6f)) ? 1 : 0;
            }
        }
        __syncthreads();

        // ---- 3x3 symmetric inverse (redundant per-thread) ----
        const float A00 = sS[0], A01 = sS[1], A02 = sS[2];
        const float A11 = sS[3], A12 = sS[4], A22 = 64.0f;
        float det = A00 * (A11 * A22 - A12 * A12)
                  - A01 * (A01 * A22 - A12 * A02)
                  + A02 * (A01 * A12 - A11 * A02);
        float i00, i01, i02, i11, i12, i22;
        if (det == 0.0f) {
            i00 = 1.0f; i01 = 0.0f; i02 = 0.0f;
            i11 = 1.0f; i12 = 0.0f; i22 = 1.0f;
        } else {
            i00 = (A11 * A22 - A12 * A12) / det;
            i01 = (A02 * A12 - A01 * A22) / det;
            i02 = (A01 * A12 - A02 * A11) / det;
            i11 = (A00 * A22 - A02 * A02) / det;
            i12 = (A01 * A02 - A00 * A12) / det;
            i22 = (A00 * A11 - A01 * A01) / det;
        }

        // ---- base = inv @ a_base (3 x 64) ----
        if (tid < 192) {
            int k = tid >> 6;
            int p = tid & 63;
            int pr = p >> 3, pc = p & 7;
            float c0 = (k == 0) ? i00 : ((k == 1) ? i01 : i02);
            float c1 = (k == 0) ? i01 : ((k == 1) ? i11 : i12);
            float c2 = (k == 0) ? i02 : ((k == 1) ? i12 : i22);
            sbase[k][pr][pc] = c0 * sa[0][pr][pc] + c1 * sa[1][pr][pc] + c2;
        }
        __syncthreads();

        // ---- p[k][img] = sum_p base[k][p] * d1[img][p] (d1 in registers) ----
        {
            float t0 = 0.0f, t1 = 0.0f, t2 = 0.0f;
            float4 b0a = *reinterpret_cast<const float4*>(&sbase[0][row][0]);
            float4 b0b = *reinterpret_cast<const float4*>(&sbase[0][row][4]);
            float4 b1a = *reinterpret_cast<const float4*>(&sbase[1][row][0]);
            float4 b1b = *reinterpret_cast<const float4*>(&sbase[1][row][4]);
            float4 b2a = *reinterpret_cast<const float4*>(&sbase[2][row][0]);
            float4 b2b = *reinterpret_cast<const float4*>(&sbase[2][row][4]);
            float bb0[8] = {b0a.x, b0a.y, b0a.z, b0a.w, b0b.x, b0b.y, b0b.z, b0b.w};
            float bb1[8] = {b1a.x, b1a.y, b1a.z, b1a.w, b1b.x, b1b.y, b1b.z, b1b.w};
            float bb2[8] = {b2a.x, b2a.y, b2a.z, b2a.w, b2b.x, b2b.y, b2b.z, b2b.w};
            #pragma unroll
            for (int c = 0; c < 8; c++) {
                t0 += bb0[c] * d1r[c];
                t1 += bb1[c] * d1r[c];
                t2 += bb2[c] * d1r[c];
            }
            #pragma unroll
            for (int o = 4; o; o >>= 1) {
                t0 += __shfl_xor_sync(0xFFFFFFFFu, t0, o);
                t1 += __shfl_xor_sync(0xFFFFFFFFu, t1, o);
                t2 += __shfl_xor_sync(0xFFFFFFFFu, t2, o);
            }
            if (row == 0) {
                sp[0][img] = t0;
                sp[1][img] = t1;
                sp[2][img] = t2;
            }
        }
        __syncthreads();

        // ---- reconstruct, quantize, loss gate; result -> smem in place ----
        {
            const bool degen = (sdegen != 0);
            const float p0 = sp[0][img], p1 = sp[1][img], p2 = sp[2][img];
            float4 a1a = *reinterpret_cast<const float4*>(&sa[0][row][0]);
            float4 a1b = *reinterpret_cast<const float4*>(&sa[0][row][4]);
            float4 a2a = *reinterpret_cast<const float4*>(&sa[1][row][0]);
            float4 a2b = *reinterpret_cast<const float4*>(&sa[1][row][4]);
            float av1[8] = {a1a.x, a1a.y, a1a.z, a1a.w, a1b.x, a1b.y, a1b.z, a1b.w};
            float av2[8] = {a2a.x, a2a.y, a2a.z, a2a.w, a2b.x, a2b.y, a2b.z, a2b.w};

            float r1v[8];
            float loss = 0.0f;
            #pragma unroll
            for (int c = 0; c < 8; c++) {
                float r = av1[c] * p0 + av2[c] * p1 + p2;
                r1v[c] = __fmul_rn(rintf(__fmul_rn(r, rlsb)), lsb);
                float d = d1r[c] - r1v[c];
                loss += d * d;
            }
            #pragma unroll
            for (int o = 4; o; o >>= 1)
                loss += __shfl_xor_sync(0xFFFFFFFFu, loss, o);

            bool sel = (!degen) && (loss <= LOSS_THR);
            float ov[8];
            #pragma unroll
            for (int c = 0; c < 8; c++) {
                float rr = sel ? r1v[c] : d1r[c];
                ov[c] = __fadd_rn(rr, xl[c]);
            }
            *reinterpret_cast<float4*>(&ss[tid][wb << 3]) =
                make_float4(ov[0], ov[1], ov[2], ov[3]);
            *reinterpret_cast<float4*>(&ss[tid][(wb << 3) + 4]) =
                make_float4(ov[4], ov[5], ov[6], ov[7]);
        }
        __syncthreads();
    }

    // ---- coalesced staged store: smem -> global ----
    #pragma unroll
    for (int k = 0; k < 8; k++) {
        int f = (k << 8) + tid;
        int seg = f >> 3;
        int j = f & 7;
        int si = seg >> 3, sr = seg & 7;
        float4 v = *reinterpret_cast<const float4*>(&ss[seg][j << 2]);
        *reinterpret_cast<float4*>(
            out + (si << 20) + (((hb << 3) + sr) << 10) + (wbg << 5) + (j << 2)) = v;
    }
    (void)gout;
}

extern "C" void kernel_launch(void* const* d_in, const int* in_sizes, int n_in,
                              void* d_out, int out_size) {
    const float* x = (const float*)d_in[0];
    float* out = (float*)d_out;
    (void)in_sizes; (void)n_in; (void)out_size;

    minmax_kernel<<<MM_BLOCKS, 256>>>(x);
    block_kernel<<<NHB * NWBG, 256>>>(x, out);
}